// round 10
// baseline (speedup 1.0000x reference)
#include <cuda_runtime.h>
#include <cuda_bf16.h>
#include <cstdint>

#define B64  64
#define TLEN 1024
#define SDIM 1024
#define G3   (3*SDIM)

// ---- scan config ----
#define NCTA   128      // persistent CTAs; each owns WT h-columns
#define WT     8        // h columns per CTA
#define NR     24       // 3*WT gate rows (r,z,n)
#define NCHUNK 8        // k-chunks of 128 per step
#define DEPTH  4        // pipeline stages (16KB each)
#define STG_W  4096     // 32-bit words per stage (64 kp x 64 b)
#define WS_STRIDE 516   // padded word stride for weight rows

// ---- device globals (allocation-free scratch) ----
__device__ float    g_xg[(size_t)TLEN * B64 * G3];        // x_gates [T][B][3S] fp32
__device__ __align__(128) unsigned g_h[2][512 * B64];     // h bf16x2, [kp][b] xor-swizzled
__device__ float    g_hT[B64 * SDIM];                     // final h, fp32 [b][k]
__device__ unsigned g_cnt;
__device__ unsigned g_gen;

// ---------------- helpers ----------------
__device__ __forceinline__ unsigned f2tf(float f) {
    unsigned u;
    asm("cvt.rna.tf32.f32 %0, %1;" : "=r"(u) : "f"(f));
    return u;
}
__device__ __forceinline__ unsigned pack_bf(float lo, float hi) {
    unsigned r;
    asm("cvt.rn.bf16x2.f32 %0, %1, %2;" : "=r"(r) : "f"(hi), "f"(lo));
    return r;
}

// tf32 m16n8k8 (phase-1 GEMM)
__device__ __forceinline__ void mma8(float c[4], const unsigned a[4], const unsigned b[2]) {
    asm volatile(
        "mma.sync.aligned.m16n8k8.row.col.f32.tf32.tf32.f32 "
        "{%0,%1,%2,%3}, {%4,%5,%6,%7}, {%8,%9}, {%0,%1,%2,%3};"
        : "+f"(c[0]), "+f"(c[1]), "+f"(c[2]), "+f"(c[3])
        : "r"(a[0]), "r"(a[1]), "r"(a[2]), "r"(a[3]),
          "r"(b[0]), "r"(b[1]));
}
// bf16 m16n8k16 (scan GEMM)
__device__ __forceinline__ void mma16(float c[4], const unsigned a[4], const unsigned b[2]) {
    asm volatile(
        "mma.sync.aligned.m16n8k16.row.col.f32.bf16.bf16.f32 "
        "{%0,%1,%2,%3}, {%4,%5,%6,%7}, {%8,%9}, {%0,%1,%2,%3};"
        : "+f"(c[0]), "+f"(c[1]), "+f"(c[2]), "+f"(c[3])
        : "r"(a[0]), "r"(a[1]), "r"(a[2]), "r"(a[3]),
          "r"(b[0]), "r"(b[1]));
}

__device__ __forceinline__ void cp16(void* s, const void* g) {
    unsigned sa = (unsigned)__cvta_generic_to_shared(s);
    asm volatile("cp.async.cg.shared.global [%0], [%1], 16;" :: "r"(sa), "l"(g));
}
__device__ __forceinline__ void cp_commit() { asm volatile("cp.async.commit_group;"); }
template<int N> __device__ __forceinline__ void cp_wait() {
    asm volatile("cp.async.wait_group %0;" :: "n"(N));
}

__device__ __forceinline__ void bulkcp(void* dst_smem, const void* src, unsigned bytes, void* mbar) {
    unsigned d = (unsigned)__cvta_generic_to_shared(dst_smem);
    unsigned m = (unsigned)__cvta_generic_to_shared(mbar);
    asm volatile("cp.async.bulk.shared::cluster.global.mbarrier::complete_tx::bytes [%0], [%1], %2, [%3];"
                 :: "r"(d), "l"(src), "r"(bytes), "r"(m) : "memory");
}
__device__ __forceinline__ void mbar_init(void* mbar, unsigned cnt) {
    unsigned m = (unsigned)__cvta_generic_to_shared(mbar);
    asm volatile("mbarrier.init.shared.b64 [%0], %1;" :: "r"(m), "r"(cnt) : "memory");
}
__device__ __forceinline__ void mbar_expect_tx(void* mbar, unsigned bytes) {
    unsigned m = (unsigned)__cvta_generic_to_shared(mbar);
    asm volatile("mbarrier.arrive.expect_tx.shared.b64 _, [%0], %1;" :: "r"(m), "r"(bytes) : "memory");
}
__device__ __forceinline__ void mbar_wait(void* mbar, unsigned parity) {
    unsigned m = (unsigned)__cvta_generic_to_shared(mbar);
    asm volatile(
        "{\n\t"
        ".reg .pred P1;\n\t"
        "WAIT_LOOP_%=:\n\t"
        "mbarrier.try_wait.parity.acquire.cta.shared::cta.b64 P1, [%0], %1, 0x989680;\n\t"
        "@P1 bra.uni WAIT_DONE_%=;\n\t"
        "bra.uni WAIT_LOOP_%=;\n\t"
        "WAIT_DONE_%=:\n\t"
        "}"
        :: "r"(m), "r"(parity) : "memory");
}

__device__ __forceinline__ void grid_barrier() {
    __syncthreads();
    if (threadIdx.x == 0) {
        unsigned gen;
        asm volatile("ld.acquire.gpu.global.u32 %0, [%1];" : "=r"(gen) : "l"(&g_gen) : "memory");
        __threadfence();
        unsigned prev = atomicAdd(&g_cnt, 1);
        if (prev == NCTA - 1) {
            g_cnt = 0;
            asm volatile("st.release.gpu.global.u32 [%0], %1;" :: "l"(&g_gen), "r"(gen + 1) : "memory");
        } else {
            unsigned cur;
            do {
                asm volatile("ld.acquire.gpu.global.u32 %0, [%1];" : "=r"(cur) : "l"(&g_gen) : "memory");
            } while (cur == gen);
        }
        __threadfence();
    }
    __syncthreads();
}

// =====================================================================
// Phase 1: x_gates (tf32 GEMM) -> [T][B][3S] fp32. Unchanged from r2.
// =====================================================================
#define XG_SMEM (2 * 2 * 128 * 36 * 4)

__global__ void __launch_bounds__(256) xg_kernel(const float* __restrict__ A,
                                                 const float* __restrict__ W,
                                                 const float* __restrict__ bias) {
    extern __shared__ float sm[];
    float* As = sm;
    float* Bs = sm + 2 * 128 * 36;

    const int tid = threadIdx.x;
    const size_t arow0 = (size_t)blockIdx.y * 128;
    const int    ncol0 = blockIdx.x * 128;

    auto load_stage = [&](int stage, int kc) {
        float* as = As + stage * 128 * 36;
        float* bs = Bs + stage * 128 * 36;
        #pragma unroll
        for (int i = 0; i < 4; i++) {
            int idx = tid + i * 256;
            int r = idx >> 3, c4 = (idx & 7) * 4;
            cp16(&as[r * 36 + c4], &A[(arow0 + r) * SDIM + kc + c4]);
            cp16(&bs[r * 36 + c4], &W[(size_t)(ncol0 + r) * SDIM + kc + c4]);
        }
    };

    const int wid = tid >> 5, lane = tid & 31, g = lane >> 2, tg = lane & 3;
    const int wm = wid & 3, wn = wid >> 2;

    float acc[2][8][4];
    #pragma unroll
    for (int i = 0; i < 2; i++)
        #pragma unroll
        for (int j = 0; j < 8; j++)
            #pragma unroll
            for (int k = 0; k < 4; k++) acc[i][j][k] = 0.f;

    load_stage(0, 0); cp_commit();
    for (int c = 0; c < SDIM / 32; ++c) {
        if (c + 1 < SDIM / 32) { load_stage((c + 1) & 1, (c + 1) * 32); cp_commit(); cp_wait<1>(); }
        else                   { cp_wait<0>(); }
        __syncthreads();
        const float* as = As + (c & 1) * 128 * 36;
        const float* bs = Bs + (c & 1) * 128 * 36;
        #pragma unroll
        for (int kk = 0; kk < 4; ++kk) {
            const int ko = kk * 8;
            unsigned a[2][4];
            #pragma unroll
            for (int mf = 0; mf < 2; ++mf) {
                int rb = wm * 32 + mf * 16;
                a[mf][0] = f2tf(as[(rb + g    ) * 36 + ko + tg    ]);
                a[mf][1] = f2tf(as[(rb + g + 8) * 36 + ko + tg    ]);
                a[mf][2] = f2tf(as[(rb + g    ) * 36 + ko + tg + 4]);
                a[mf][3] = f2tf(as[(rb + g + 8) * 36 + ko + tg + 4]);
            }
            #pragma unroll
            for (int nf = 0; nf < 8; ++nf) {
                int nb = wn * 64 + nf * 8 + g;
                unsigned b2[2];
                b2[0] = f2tf(bs[nb * 36 + ko + tg    ]);
                b2[1] = f2tf(bs[nb * 36 + ko + tg + 4]);
                mma8(acc[0][nf], a[0], b2);
                mma8(acc[1][nf], a[1], b2);
            }
        }
        __syncthreads();
    }
    #pragma unroll
    for (int mf = 0; mf < 2; ++mf) {
        #pragma unroll
        for (int nf = 0; nf < 8; ++nf) {
            int col = ncol0 + wn * 64 + nf * 8 + 2 * tg;
            float b0 = bias[col], b1 = bias[col + 1];
            size_t row = arow0 + wm * 32 + mf * 16 + g;       // = b*T + t
            size_t bb = row >> 10, tt = row & 1023;
            size_t orow0s = (tt << 6) + bb;
            size_t orow1s = orow0s + (8 << 6);
            float2 v0 = { acc[mf][nf][0] + b0, acc[mf][nf][1] + b1 };
            float2 v1 = { acc[mf][nf][2] + b0, acc[mf][nf][3] + b1 };
            *(float2*)&g_xg[orow0s * G3 + col] = v0;
            *(float2*)&g_xg[orow1s * G3 + col] = v1;
        }
    }
}

// =====================================================================
// Phase 2: persistent GRU scan, bf16 exchange + bf16 mma.
// 128 CTAs x 256 thr. CTA owns h cols [8c,8c+8) -> 24 gate rows (bf16,
// 24x1024 in SMEM, 49.5KB). h exchanged as bf16x2 [kp][b] (xor-swizzled),
// streamed in 8 chunks of 16KB via 4-stage bulk-copy pipeline.
// Warp w covers m=64 x its k16 slice per chunk; 8 k-partials reduced in
// SMEM. fp32 state kept in registers. x_gates prefetched via cp.async.
// =====================================================================
// smem words: 16 (mbar) + 4*4096 (stages) + 24*516 (ws) + 8*64*24 (hgs) + 1536 (xgs)
#define SCAN_SMEM ((16 + DEPTH*STG_W + NR*WS_STRIDE + 8*B64*NR + B64*NR) * 4)

__global__ void __launch_bounds__(256, 1) scan_kernel(const float* __restrict__ W_hh,
                                                      const float* __restrict__ b_hh) {
    extern __shared__ float sm[];
    uint64_t* mbar = (uint64_t*)sm;                     // 4 barriers
    float*    stg  = sm + 16;                           // 4 x 4096 words
    unsigned* ws   = (unsigned*)(stg + DEPTH * STG_W);  // 24 x 516 bf16x2 words
    float*    hgs  = (float*)(ws + NR * WS_STRIDE);     // 8 x 64 x 24 fp32 partials
    float*    xgs  = hgs + 8 * B64 * NR;                // 64 x 3 x 8 fp32

    const int tid  = threadIdx.x;
    const int col0 = blockIdx.x * WT;

    // ---- init: weights -> bf16x2 smem. rows [r(8); z(8); n(8)] of cols col0..col0+7
    for (int i = tid; i < NR * 512; i += 256) {
        int rr = i >> 9, kp = i & 511;
        int row = (rr >> 3) * SDIM + col0 + (rr & 7);
        const float2 v = *(const float2*)&W_hh[(size_t)row * SDIM + 2 * kp];
        ws[rr * WS_STRIDE + kp] = pack_bf(v.x, v.y);
    }
    // ---- zero own slice of h buffer 0
    {
        int b = tid >> 2, j2 = tid & 3;
        int kp = (col0 >> 1) + j2;
        g_h[0][kp * 64 + (b ^ (j2 << 3))] = 0u;
    }
    if (tid == 0)
        #pragma unroll
        for (int s = 0; s < DEPTH; ++s) mbar_init(&mbar[s], 1);

    // per-thread pointwise identity + persistent fp32 state + biases in regs
    const int pb = tid >> 2, pj2 = tid & 3;
    const int pc0 = col0 + 2 * pj2;
    float h0 = 0.f, h1 = 0.f;
    const float br0 = b_hh[pc0],            br1 = b_hh[pc0 + 1];
    const float bz0 = b_hh[SDIM + pc0],     bz1 = b_hh[SDIM + pc0 + 1];
    const float bn0 = b_hh[2 * SDIM + pc0], bn1 = b_hh[2 * SDIM + pc0 + 1];

    grid_barrier();

    const int w = tid >> 5, lane = tid & 31, g = lane >> 2, tg = lane & 3;
    const unsigned aoff  = (unsigned)((w * 8 + tg) * 64);   // stage word base for this thread's k16
    const unsigned asw   = (unsigned)(tg << 3);             // xor swizzle
    unsigned ph[DEPTH] = {0u, 0u, 0u, 0u};

    for (int t = 0; t < TLEN; ++t) {
        const unsigned* __restrict__ hcur = g_h[t & 1];
        unsigned*       __restrict__ hnxt = g_h[(t + 1) & 1];

        // prefetch this step's x_gates slice (consumed in epilogue)
        if (tid < 192) {
            int gate = tid >> 6, b = tid & 63;
            const float* src = &g_xg[(((size_t)t << 6) + b) * G3 + gate * SDIM + col0];
            float* dst = &xgs[b * 24 + gate * 8];
            cp16(dst, src);
            cp16(dst + 4, src + 4);
        }
        cp_commit();

        // prime pipeline: chunks 0..3
        if (tid == 0) {
            #pragma unroll
            for (int s = 0; s < DEPTH; ++s) {
                mbar_expect_tx(&mbar[s], STG_W * 4);
                bulkcp(stg + s * STG_W, hcur + s * STG_W, STG_W * 4, &mbar[s]);
            }
        }

        float acc[4][3][4];
        #pragma unroll
        for (int i = 0; i < 4; i++)
            #pragma unroll
            for (int j = 0; j < 3; j++)
                #pragma unroll
                for (int k = 0; k < 4; k++) acc[i][j][k] = 0.f;

        for (int c = 0; c < NCHUNK; ++c) {
            const int s = c & (DEPTH - 1);
            mbar_wait(&mbar[s], ph[s]);
            ph[s] ^= 1u;

            const unsigned* hb = (const unsigned*)(stg + s * STG_W) + aoff;
            unsigned a[4][4];
            #pragma unroll
            for (int mf = 0; mf < 4; ++mf) {
                unsigned m0 = (unsigned)(mf * 16 + g);
                a[mf][0] = hb[        (m0      ) ^ asw];
                a[mf][1] = hb[        (m0 + 8u ) ^ asw];
                a[mf][2] = hb[256u + ((m0      ) ^ asw)];
                a[mf][3] = hb[256u + ((m0 + 8u ) ^ asw)];
            }
            const int kw = c * 64 + w * 8 + tg;
            #pragma unroll
            for (int nf = 0; nf < 3; ++nf) {
                unsigned b2[2];
                const unsigned* wr = ws + (nf * 8 + g) * WS_STRIDE + kw;
                b2[0] = wr[0];
                b2[1] = wr[4];
                #pragma unroll
                for (int mf = 0; mf < 4; ++mf) mma16(acc[mf][nf], a[mf], b2);
            }
            __syncthreads();                 // stage s fully consumed
            if (tid == 0 && c + DEPTH < NCHUNK) {
                mbar_expect_tx(&mbar[s], STG_W * 4);
                bulkcp(stg + s * STG_W, hcur + (c + DEPTH) * STG_W, STG_W * 4, &mbar[s]);
            }
        }

        cp_wait<0>();                        // x_gates slice landed
        // stage k-partials
        #pragma unroll
        for (int mf = 0; mf < 4; ++mf) {
            #pragma unroll
            for (int nf = 0; nf < 3; ++nf) {
                int m = mf * 16 + g;
                int n = nf * 8 + 2 * tg;
                float* dst = &hgs[w * (B64 * NR) + m * NR + n];
                dst[0]          = acc[mf][nf][0];
                dst[1]          = acc[mf][nf][1];
                dst[8 * NR]     = acc[mf][nf][2];
                dst[8 * NR + 1] = acc[mf][nf][3];
            }
        }
        __syncthreads();

        // pointwise GRU update: thread owns (pb, cols pc0, pc0+1)
        {
            float hr0 = br0, hr1 = br1, hz0 = bz0, hz1 = bz1, hn0 = bn0, hn1 = bn1;
            #pragma unroll
            for (int q = 0; q < 8; ++q) {
                const float* base = &hgs[q * (B64 * NR) + pb * NR + 2 * pj2];
                hr0 += base[0];  hr1 += base[1];
                hz0 += base[8];  hz1 += base[9];
                hn0 += base[16]; hn1 += base[17];
            }
            const float* xr = &xgs[pb * 24 + 2 * pj2];
            float r0 = 1.f / (1.f + __expf(-(xr[0]  + hr0)));
            float r1 = 1.f / (1.f + __expf(-(xr[1]  + hr1)));
            float z0 = 1.f / (1.f + __expf(-(xr[8]  + hz0)));
            float z1 = 1.f / (1.f + __expf(-(xr[9]  + hz1)));
            float p0 = xr[16] + r0 * hn0;
            float p1 = xr[17] + r1 * hn1;
            float n0 = 2.f / (1.f + __expf(-2.f * p0)) - 1.f;
            float n1 = 2.f / (1.f + __expf(-2.f * p1)) - 1.f;
            h0 = (1.f - z0) * n0 + z0 * h0;
            h1 = (1.f - z1) * n1 + z1 * h1;
            int kp = (col0 >> 1) + pj2;
            hnxt[kp * 64 + (pb ^ (pj2 << 3))] = pack_bf(h0, h1);
            if (t == TLEN - 1) {
                g_hT[pb * SDIM + pc0]     = h0;
                g_hT[pb * SDIM + pc0 + 1] = h1;
            }
        }
        grid_barrier();
    }
}

// =====================================================================
// Phase 3: out[b] = sigmoid(g_hT[b] . W_out + b_out), fp32.
// =====================================================================
__global__ void final_kernel(const float* __restrict__ W_out,
                             const float* __restrict__ b_out,
                             float* __restrict__ out) {
    int wid = threadIdx.x >> 5, lane = threadIdx.x & 31;
    for (int b = wid; b < B64; b += 8) {
        const float* h = &g_hT[b * SDIM];
        float s = 0.f;
        for (int k = lane; k < SDIM; k += 32) s += h[k] * W_out[k];
        #pragma unroll
        for (int o = 16; o; o >>= 1) s += __shfl_xor_sync(0xffffffffu, s, o);
        if (lane == 0) out[b] = 1.f / (1.f + __expf(-(s + b_out[0])));
    }
}

// =====================================================================
extern "C" void kernel_launch(void* const* d_in, const int* in_sizes, int n_in,
                              void* d_out, int out_size) {
    const float* batch = (const float*)d_in[0];
    const float* W_ih  = (const float*)d_in[1];
    const float* W_hh  = (const float*)d_in[2];
    const float* b_ih  = (const float*)d_in[3];
    const float* b_hh  = (const float*)d_in[4];
    const float* W_out = (const float*)d_in[5];
    const float* b_out = (const float*)d_in[6];
    float* out = (float*)d_out;

    (void)in_sizes; (void)n_in; (void)out_size;

    cudaFuncSetAttribute(xg_kernel,   cudaFuncAttributeMaxDynamicSharedMemorySize, XG_SMEM);
    cudaFuncSetAttribute(scan_kernel, cudaFuncAttributeMaxDynamicSharedMemorySize, SCAN_SMEM);

    xg_kernel<<<dim3(G3 / 128, (B64 * TLEN) / 128), 256, XG_SMEM>>>(batch, W_ih, b_ih);
    scan_kernel<<<NCTA, 256, SCAN_SMEM>>>(W_hh, b_hh);
    final_kernel<<<1, 256>>>(W_out, b_out, out);
}

// round 11
// speedup vs baseline: 1.0043x; 1.0043x over previous
#include <cuda_runtime.h>
#include <cuda_bf16.h>
#include <cstdint>

#define B64  64
#define TLEN 1024
#define SDIM 1024
#define G3   (3*SDIM)

// ---- scan config ----
#define NCTA   128      // persistent CTAs; each owns WT h-columns
#define WT     8        // h columns per CTA
#define NR     24       // 3*WT gate rows (r,z,n)
#define NCHUNK 8        // k-chunks of 128 per step
#define DEPTH  4        // pipeline stages (16KB each)
#define STG_W  4096     // 32-bit words per stage (64 kp x 64 b)
#define WS_STRIDE 516   // padded word stride for weight rows

// ---- device globals (allocation-free scratch) ----
__device__ float    g_xg[(size_t)TLEN * B64 * G3];        // x_gates [T][B][3S] fp32
__device__ __align__(128) unsigned g_h[2][512 * B64];     // h bf16x2, [kp][b] xor-swizzled
__device__ float    g_hT[B64 * SDIM];                     // final h, fp32 [b][k]
__device__ unsigned g_cnt;
__device__ unsigned g_gen;

// ---------------- helpers ----------------
__device__ __forceinline__ unsigned f2tf(float f) {
    unsigned u;
    asm("cvt.rna.tf32.f32 %0, %1;" : "=r"(u) : "f"(f));
    return u;
}
__device__ __forceinline__ unsigned pack_bf(float lo, float hi) {
    unsigned r;
    asm("cvt.rn.bf16x2.f32 %0, %1, %2;" : "=r"(r) : "f"(hi), "f"(lo));
    return r;
}

// tf32 m16n8k8 (phase-1 GEMM)
__device__ __forceinline__ void mma8(float c[4], const unsigned a[4], const unsigned b[2]) {
    asm volatile(
        "mma.sync.aligned.m16n8k8.row.col.f32.tf32.tf32.f32 "
        "{%0,%1,%2,%3}, {%4,%5,%6,%7}, {%8,%9}, {%0,%1,%2,%3};"
        : "+f"(c[0]), "+f"(c[1]), "+f"(c[2]), "+f"(c[3])
        : "r"(a[0]), "r"(a[1]), "r"(a[2]), "r"(a[3]),
          "r"(b[0]), "r"(b[1]));
}
// bf16 m16n8k16 (scan GEMM)
__device__ __forceinline__ void mma16(float c[4], const unsigned a[4], const unsigned b[2]) {
    asm volatile(
        "mma.sync.aligned.m16n8k16.row.col.f32.bf16.bf16.f32 "
        "{%0,%1,%2,%3}, {%4,%5,%6,%7}, {%8,%9}, {%0,%1,%2,%3};"
        : "+f"(c[0]), "+f"(c[1]), "+f"(c[2]), "+f"(c[3])
        : "r"(a[0]), "r"(a[1]), "r"(a[2]), "r"(a[3]),
          "r"(b[0]), "r"(b[1]));
}

__device__ __forceinline__ void cp16(void* s, const void* g) {
    unsigned sa = (unsigned)__cvta_generic_to_shared(s);
    asm volatile("cp.async.cg.shared.global [%0], [%1], 16;" :: "r"(sa), "l"(g));
}
__device__ __forceinline__ void cp_commit() { asm volatile("cp.async.commit_group;"); }
template<int N> __device__ __forceinline__ void cp_wait() {
    asm volatile("cp.async.wait_group %0;" :: "n"(N));
}

__device__ __forceinline__ void bulkcp(void* dst_smem, const void* src, unsigned bytes, void* mbar) {
    unsigned d = (unsigned)__cvta_generic_to_shared(dst_smem);
    unsigned m = (unsigned)__cvta_generic_to_shared(mbar);
    asm volatile("cp.async.bulk.shared::cluster.global.mbarrier::complete_tx::bytes [%0], [%1], %2, [%3];"
                 :: "r"(d), "l"(src), "r"(bytes), "r"(m) : "memory");
}
__device__ __forceinline__ void mbar_init(void* mbar, unsigned cnt) {
    unsigned m = (unsigned)__cvta_generic_to_shared(mbar);
    asm volatile("mbarrier.init.shared.b64 [%0], %1;" :: "r"(m), "r"(cnt) : "memory");
}
__device__ __forceinline__ void mbar_expect_tx(void* mbar, unsigned bytes) {
    unsigned m = (unsigned)__cvta_generic_to_shared(mbar);
    asm volatile("mbarrier.arrive.expect_tx.shared.b64 _, [%0], %1;" :: "r"(m), "r"(bytes) : "memory");
}
__device__ __forceinline__ void mbar_wait(void* mbar, unsigned parity) {
    unsigned m = (unsigned)__cvta_generic_to_shared(mbar);
    asm volatile(
        "{\n\t"
        ".reg .pred P1;\n\t"
        "WAIT_LOOP_%=:\n\t"
        "mbarrier.try_wait.parity.acquire.cta.shared::cta.b64 P1, [%0], %1, 0x989680;\n\t"
        "@P1 bra.uni WAIT_DONE_%=;\n\t"
        "bra.uni WAIT_LOOP_%=;\n\t"
        "WAIT_DONE_%=:\n\t"
        "}"
        :: "r"(m), "r"(parity) : "memory");
}

__device__ __forceinline__ void grid_barrier() {
    __syncthreads();
    if (threadIdx.x == 0) {
        unsigned gen;
        asm volatile("ld.acquire.gpu.global.u32 %0, [%1];" : "=r"(gen) : "l"(&g_gen) : "memory");
        __threadfence();
        unsigned prev = atomicAdd(&g_cnt, 1);
        if (prev == NCTA - 1) {
            g_cnt = 0;
            asm volatile("st.release.gpu.global.u32 [%0], %1;" :: "l"(&g_gen), "r"(gen + 1) : "memory");
        } else {
            unsigned cur;
            do {
                asm volatile("ld.acquire.gpu.global.u32 %0, [%1];" : "=r"(cur) : "l"(&g_gen) : "memory");
            } while (cur == gen);
        }
        __threadfence();
    }
    __syncthreads();
}

// =====================================================================
// Phase 1: x_gates (tf32 GEMM) -> [T][B][3S] fp32. Unchanged from r2.
// =====================================================================
#define XG_SMEM (2 * 2 * 128 * 36 * 4)

__global__ void __launch_bounds__(256) xg_kernel(const float* __restrict__ A,
                                                 const float* __restrict__ W,
                                                 const float* __restrict__ bias) {
    extern __shared__ float sm[];
    float* As = sm;
    float* Bs = sm + 2 * 128 * 36;

    const int tid = threadIdx.x;
    const size_t arow0 = (size_t)blockIdx.y * 128;
    const int    ncol0 = blockIdx.x * 128;

    auto load_stage = [&](int stage, int kc) {
        float* as = As + stage * 128 * 36;
        float* bs = Bs + stage * 128 * 36;
        #pragma unroll
        for (int i = 0; i < 4; i++) {
            int idx = tid + i * 256;
            int r = idx >> 3, c4 = (idx & 7) * 4;
            cp16(&as[r * 36 + c4], &A[(arow0 + r) * SDIM + kc + c4]);
            cp16(&bs[r * 36 + c4], &W[(size_t)(ncol0 + r) * SDIM + kc + c4]);
        }
    };

    const int wid = tid >> 5, lane = tid & 31, g = lane >> 2, tg = lane & 3;
    const int wm = wid & 3, wn = wid >> 2;

    float acc[2][8][4];
    #pragma unroll
    for (int i = 0; i < 2; i++)
        #pragma unroll
        for (int j = 0; j < 8; j++)
            #pragma unroll
            for (int k = 0; k < 4; k++) acc[i][j][k] = 0.f;

    load_stage(0, 0); cp_commit();
    for (int c = 0; c < SDIM / 32; ++c) {
        if (c + 1 < SDIM / 32) { load_stage((c + 1) & 1, (c + 1) * 32); cp_commit(); cp_wait<1>(); }
        else                   { cp_wait<0>(); }
        __syncthreads();
        const float* as = As + (c & 1) * 128 * 36;
        const float* bs = Bs + (c & 1) * 128 * 36;
        #pragma unroll
        for (int kk = 0; kk < 4; ++kk) {
            const int ko = kk * 8;
            unsigned a[2][4];
            #pragma unroll
            for (int mf = 0; mf < 2; ++mf) {
                int rb = wm * 32 + mf * 16;
                a[mf][0] = f2tf(as[(rb + g    ) * 36 + ko + tg    ]);
                a[mf][1] = f2tf(as[(rb + g + 8) * 36 + ko + tg    ]);
                a[mf][2] = f2tf(as[(rb + g    ) * 36 + ko + tg + 4]);
                a[mf][3] = f2tf(as[(rb + g + 8) * 36 + ko + tg + 4]);
            }
            #pragma unroll
            for (int nf = 0; nf < 8; ++nf) {
                int nb = wn * 64 + nf * 8 + g;
                unsigned b2[2];
                b2[0] = f2tf(bs[nb * 36 + ko + tg    ]);
                b2[1] = f2tf(bs[nb * 36 + ko + tg + 4]);
                mma8(acc[0][nf], a[0], b2);
                mma8(acc[1][nf], a[1], b2);
            }
        }
        __syncthreads();
    }
    #pragma unroll
    for (int mf = 0; mf < 2; ++mf) {
        #pragma unroll
        for (int nf = 0; nf < 8; ++nf) {
            int col = ncol0 + wn * 64 + nf * 8 + 2 * tg;
            float b0 = bias[col], b1 = bias[col + 1];
            size_t row = arow0 + wm * 32 + mf * 16 + g;       // = b*T + t
            size_t bb = row >> 10, tt = row & 1023;
            size_t orow0s = (tt << 6) + bb;
            size_t orow1s = orow0s + (8 << 6);
            float2 v0 = { acc[mf][nf][0] + b0, acc[mf][nf][1] + b1 };
            float2 v1 = { acc[mf][nf][2] + b0, acc[mf][nf][3] + b1 };
            *(float2*)&g_xg[orow0s * G3 + col] = v0;
            *(float2*)&g_xg[orow1s * G3 + col] = v1;
        }
    }
}

// =====================================================================
// Phase 2: persistent GRU scan, bf16 exchange + bf16 mma.
// 128 CTAs x 256 thr. CTA owns h cols [8c,8c+8) -> 24 gate rows (bf16,
// 24x1024 in SMEM, 49.5KB). h exchanged as bf16x2 [kp][b] (xor-swizzled),
// streamed in 8 chunks of 16KB via 4-stage bulk-copy pipeline.
// Warp w covers m=64 x its k16 slice per chunk; 8 k-partials reduced in
// SMEM. fp32 state kept in registers. x_gates prefetched via cp.async.
// =====================================================================
// smem words: 16 (mbar) + 4*4096 (stages) + 24*516 (ws) + 8*64*24 (hgs) + 1536 (xgs)
#define SCAN_SMEM ((16 + DEPTH*STG_W + NR*WS_STRIDE + 8*B64*NR + B64*NR) * 4)

__global__ void __launch_bounds__(256, 1) scan_kernel(const float* __restrict__ W_hh,
                                                      const float* __restrict__ b_hh) {
    extern __shared__ float sm[];
    uint64_t* mbar = (uint64_t*)sm;                     // 4 barriers
    float*    stg  = sm + 16;                           // 4 x 4096 words
    unsigned* ws   = (unsigned*)(stg + DEPTH * STG_W);  // 24 x 516 bf16x2 words
    float*    hgs  = (float*)(ws + NR * WS_STRIDE);     // 8 x 64 x 24 fp32 partials
    float*    xgs  = hgs + 8 * B64 * NR;                // 64 x 3 x 8 fp32

    const int tid  = threadIdx.x;
    const int col0 = blockIdx.x * WT;

    // ---- init: weights -> bf16x2 smem. rows [r(8); z(8); n(8)] of cols col0..col0+7
    for (int i = tid; i < NR * 512; i += 256) {
        int rr = i >> 9, kp = i & 511;
        int row = (rr >> 3) * SDIM + col0 + (rr & 7);
        const float2 v = *(const float2*)&W_hh[(size_t)row * SDIM + 2 * kp];
        ws[rr * WS_STRIDE + kp] = pack_bf(v.x, v.y);
    }
    // ---- zero own slice of h buffer 0
    {
        int b = tid >> 2, j2 = tid & 3;
        int kp = (col0 >> 1) + j2;
        g_h[0][kp * 64 + (b ^ (j2 << 3))] = 0u;
    }
    if (tid == 0)
        #pragma unroll
        for (int s = 0; s < DEPTH; ++s) mbar_init(&mbar[s], 1);

    // per-thread pointwise identity + persistent fp32 state + biases in regs
    const int pb = tid >> 2, pj2 = tid & 3;
    const int pc0 = col0 + 2 * pj2;
    float h0 = 0.f, h1 = 0.f;
    const float br0 = b_hh[pc0],            br1 = b_hh[pc0 + 1];
    const float bz0 = b_hh[SDIM + pc0],     bz1 = b_hh[SDIM + pc0 + 1];
    const float bn0 = b_hh[2 * SDIM + pc0], bn1 = b_hh[2 * SDIM + pc0 + 1];

    grid_barrier();

    const int w = tid >> 5, lane = tid & 31, g = lane >> 2, tg = lane & 3;
    const unsigned aoff  = (unsigned)((w * 8 + tg) * 64);   // stage word base for this thread's k16
    const unsigned asw   = (unsigned)(tg << 3);             // xor swizzle
    unsigned ph[DEPTH] = {0u, 0u, 0u, 0u};

    for (int t = 0; t < TLEN; ++t) {
        const unsigned* __restrict__ hcur = g_h[t & 1];
        unsigned*       __restrict__ hnxt = g_h[(t + 1) & 1];

        // prefetch this step's x_gates slice (consumed in epilogue)
        if (tid < 192) {
            int gate = tid >> 6, b = tid & 63;
            const float* src = &g_xg[(((size_t)t << 6) + b) * G3 + gate * SDIM + col0];
            float* dst = &xgs[b * 24 + gate * 8];
            cp16(dst, src);
            cp16(dst + 4, src + 4);
        }
        cp_commit();

        // prime pipeline: chunks 0..3
        if (tid == 0) {
            #pragma unroll
            for (int s = 0; s < DEPTH; ++s) {
                mbar_expect_tx(&mbar[s], STG_W * 4);
                bulkcp(stg + s * STG_W, hcur + s * STG_W, STG_W * 4, &mbar[s]);
            }
        }

        float acc[4][3][4];
        #pragma unroll
        for (int i = 0; i < 4; i++)
            #pragma unroll
            for (int j = 0; j < 3; j++)
                #pragma unroll
                for (int k = 0; k < 4; k++) acc[i][j][k] = 0.f;

        for (int c = 0; c < NCHUNK; ++c) {
            const int s = c & (DEPTH - 1);
            mbar_wait(&mbar[s], ph[s]);
            ph[s] ^= 1u;

            const unsigned* hb = (const unsigned*)(stg + s * STG_W) + aoff;
            unsigned a[4][4];
            #pragma unroll
            for (int mf = 0; mf < 4; ++mf) {
                unsigned m0 = (unsigned)(mf * 16 + g);
                a[mf][0] = hb[        (m0      ) ^ asw];
                a[mf][1] = hb[        (m0 + 8u ) ^ asw];
                a[mf][2] = hb[256u + ((m0      ) ^ asw)];
                a[mf][3] = hb[256u + ((m0 + 8u ) ^ asw)];
            }
            const int kw = c * 64 + w * 8 + tg;
            #pragma unroll
            for (int nf = 0; nf < 3; ++nf) {
                unsigned b2[2];
                const unsigned* wr = ws + (nf * 8 + g) * WS_STRIDE + kw;
                b2[0] = wr[0];
                b2[1] = wr[4];
                #pragma unroll
                for (int mf = 0; mf < 4; ++mf) mma16(acc[mf][nf], a[mf], b2);
            }
            __syncthreads();                 // stage s fully consumed
            if (tid == 0 && c + DEPTH < NCHUNK) {
                mbar_expect_tx(&mbar[s], STG_W * 4);
                bulkcp(stg + s * STG_W, hcur + (c + DEPTH) * STG_W, STG_W * 4, &mbar[s]);
            }
        }

        cp_wait<0>();                        // x_gates slice landed
        // stage k-partials
        #pragma unroll
        for (int mf = 0; mf < 4; ++mf) {
            #pragma unroll
            for (int nf = 0; nf < 3; ++nf) {
                int m = mf * 16 + g;
                int n = nf * 8 + 2 * tg;
                float* dst = &hgs[w * (B64 * NR) + m * NR + n];
                dst[0]          = acc[mf][nf][0];
                dst[1]          = acc[mf][nf][1];
                dst[8 * NR]     = acc[mf][nf][2];
                dst[8 * NR + 1] = acc[mf][nf][3];
            }
        }
        __syncthreads();

        // pointwise GRU update: thread owns (pb, cols pc0, pc0+1)
        {
            float hr0 = br0, hr1 = br1, hz0 = bz0, hz1 = bz1, hn0 = bn0, hn1 = bn1;
            #pragma unroll
            for (int q = 0; q < 8; ++q) {
                const float* base = &hgs[q * (B64 * NR) + pb * NR + 2 * pj2];
                hr0 += base[0];  hr1 += base[1];
                hz0 += base[8];  hz1 += base[9];
                hn0 += base[16]; hn1 += base[17];
            }
            const float* xr = &xgs[pb * 24 + 2 * pj2];
            float r0 = 1.f / (1.f + __expf(-(xr[0]  + hr0)));
            float r1 = 1.f / (1.f + __expf(-(xr[1]  + hr1)));
            float z0 = 1.f / (1.f + __expf(-(xr[8]  + hz0)));
            float z1 = 1.f / (1.f + __expf(-(xr[9]  + hz1)));
            float p0 = xr[16] + r0 * hn0;
            float p1 = xr[17] + r1 * hn1;
            float n0 = 2.f / (1.f + __expf(-2.f * p0)) - 1.f;
            float n1 = 2.f / (1.f + __expf(-2.f * p1)) - 1.f;
            h0 = (1.f - z0) * n0 + z0 * h0;
            h1 = (1.f - z1) * n1 + z1 * h1;
            int kp = (col0 >> 1) + pj2;
            hnxt[kp * 64 + (pb ^ (pj2 << 3))] = pack_bf(h0, h1);
            if (t == TLEN - 1) {
                g_hT[pb * SDIM + pc0]     = h0;
                g_hT[pb * SDIM + pc0 + 1] = h1;
            }
        }
        grid_barrier();
    }
}

// =====================================================================
// Phase 3: out[b] = sigmoid(g_hT[b] . W_out + b_out), fp32.
// =====================================================================
__global__ void final_kernel(const float* __restrict__ W_out,
                             const float* __restrict__ b_out,
                             float* __restrict__ out) {
    int wid = threadIdx.x >> 5, lane = threadIdx.x & 31;
    for (int b = wid; b < B64; b += 8) {
        const float* h = &g_hT[b * SDIM];
        float s = 0.f;
        for (int k = lane; k < SDIM; k += 32) s += h[k] * W_out[k];
        #pragma unroll
        for (int o = 16; o; o >>= 1) s += __shfl_xor_sync(0xffffffffu, s, o);
        if (lane == 0) out[b] = 1.f / (1.f + __expf(-(s + b_out[0])));
    }
}

// =====================================================================
extern "C" void kernel_launch(void* const* d_in, const int* in_sizes, int n_in,
                              void* d_out, int out_size) {
    const float* batch = (const float*)d_in[0];
    const float* W_ih  = (const float*)d_in[1];
    const float* W_hh  = (const float*)d_in[2];
    const float* b_ih  = (const float*)d_in[3];
    const float* b_hh  = (const float*)d_in[4];
    const float* W_out = (const float*)d_in[5];
    const float* b_out = (const float*)d_in[6];
    float* out = (float*)d_out;

    (void)in_sizes; (void)n_in; (void)out_size;

    cudaFuncSetAttribute(xg_kernel,   cudaFuncAttributeMaxDynamicSharedMemorySize, XG_SMEM);
    cudaFuncSetAttribute(scan_kernel, cudaFuncAttributeMaxDynamicSharedMemorySize, SCAN_SMEM);

    xg_kernel<<<dim3(G3 / 128, (B64 * TLEN) / 128), 256, XG_SMEM>>>(batch, W_ih, b_ih);
    scan_kernel<<<NCTA, 256, SCAN_SMEM>>>(W_hh, b_hh);
    final_kernel<<<1, 256>>>(W_out, b_out, out);
}

// round 12
// speedup vs baseline: 1.0080x; 1.0036x over previous
#include <cuda_runtime.h>
#include <cuda_bf16.h>
#include <cstdint>

#define B64  64
#define TLEN 1024
#define SDIM 1024
#define G3   (3*SDIM)

// ---- scan config ----
#define NCTA   128      // persistent CTAs; each owns WT h-columns
#define WT     8        // h columns per CTA
#define NR     24       // 3*WT gate rows (r,z,n)
#define NCHUNK 8        // k-chunks of 128 per step
#define DEPTH  4        // pipeline stages (16KB each)
#define STG_W  4096     // 32-bit words per stage (64 kp x 64 b)
#define WS_STRIDE 516   // padded word stride for weight rows

// ---- device globals (allocation-free scratch) ----
__device__ float    g_xg[(size_t)TLEN * B64 * G3];        // x_gates [T][B][3S] fp32
__device__ __align__(128) unsigned g_h[2][512 * B64];     // h bf16x2, [kp][b] xor-swizzled
__device__ float    g_hT[B64 * SDIM];                     // final h, fp32 [b][k]
__device__ unsigned g_cnt;
__device__ unsigned g_gen;

// ---------------- helpers ----------------
__device__ __forceinline__ unsigned f2tf(float f) {
    unsigned u;
    asm("cvt.rna.tf32.f32 %0, %1;" : "=r"(u) : "f"(f));
    return u;
}
__device__ __forceinline__ unsigned pack_bf(float lo, float hi) {
    unsigned r;
    asm("cvt.rn.bf16x2.f32 %0, %1, %2;" : "=r"(r) : "f"(hi), "f"(lo));
    return r;
}

// tf32 m16n8k8 (phase-1 GEMM)
__device__ __forceinline__ void mma8(float c[4], const unsigned a[4], const unsigned b[2]) {
    asm volatile(
        "mma.sync.aligned.m16n8k8.row.col.f32.tf32.tf32.f32 "
        "{%0,%1,%2,%3}, {%4,%5,%6,%7}, {%8,%9}, {%0,%1,%2,%3};"
        : "+f"(c[0]), "+f"(c[1]), "+f"(c[2]), "+f"(c[3])
        : "r"(a[0]), "r"(a[1]), "r"(a[2]), "r"(a[3]),
          "r"(b[0]), "r"(b[1]));
}
// bf16 m16n8k16 (scan GEMM)
__device__ __forceinline__ void mma16(float c[4], const unsigned a[4], const unsigned b[2]) {
    asm volatile(
        "mma.sync.aligned.m16n8k16.row.col.f32.bf16.bf16.f32 "
        "{%0,%1,%2,%3}, {%4,%5,%6,%7}, {%8,%9}, {%0,%1,%2,%3};"
        : "+f"(c[0]), "+f"(c[1]), "+f"(c[2]), "+f"(c[3])
        : "r"(a[0]), "r"(a[1]), "r"(a[2]), "r"(a[3]),
          "r"(b[0]), "r"(b[1]));
}

__device__ __forceinline__ void cp16(void* s, const void* g) {
    unsigned sa = (unsigned)__cvta_generic_to_shared(s);
    asm volatile("cp.async.cg.shared.global [%0], [%1], 16;" :: "r"(sa), "l"(g));
}
__device__ __forceinline__ void cp_commit() { asm volatile("cp.async.commit_group;"); }
template<int N> __device__ __forceinline__ void cp_wait() {
    asm volatile("cp.async.wait_group %0;" :: "n"(N));
}

__device__ __forceinline__ void bulkcp(void* dst_smem, const void* src, unsigned bytes, void* mbar) {
    unsigned d = (unsigned)__cvta_generic_to_shared(dst_smem);
    unsigned m = (unsigned)__cvta_generic_to_shared(mbar);
    asm volatile("cp.async.bulk.shared::cluster.global.mbarrier::complete_tx::bytes [%0], [%1], %2, [%3];"
                 :: "r"(d), "l"(src), "r"(bytes), "r"(m) : "memory");
}
__device__ __forceinline__ void mbar_init(void* mbar, unsigned cnt) {
    unsigned m = (unsigned)__cvta_generic_to_shared(mbar);
    asm volatile("mbarrier.init.shared.b64 [%0], %1;" :: "r"(m), "r"(cnt) : "memory");
}
__device__ __forceinline__ void mbar_expect_tx(void* mbar, unsigned bytes) {
    unsigned m = (unsigned)__cvta_generic_to_shared(mbar);
    asm volatile("mbarrier.arrive.expect_tx.shared.b64 _, [%0], %1;" :: "r"(m), "r"(bytes) : "memory");
}
__device__ __forceinline__ void mbar_wait(void* mbar, unsigned parity) {
    unsigned m = (unsigned)__cvta_generic_to_shared(mbar);
    asm volatile(
        "{\n\t"
        ".reg .pred P1;\n\t"
        "WAIT_LOOP_%=:\n\t"
        "mbarrier.try_wait.parity.acquire.cta.shared::cta.b64 P1, [%0], %1, 0x989680;\n\t"
        "@P1 bra.uni WAIT_DONE_%=;\n\t"
        "bra.uni WAIT_LOOP_%=;\n\t"
        "WAIT_DONE_%=:\n\t"
        "}"
        :: "r"(m), "r"(parity) : "memory");
}

__device__ __forceinline__ void grid_barrier() {
    __syncthreads();
    if (threadIdx.x == 0) {
        unsigned gen;
        asm volatile("ld.acquire.gpu.global.u32 %0, [%1];" : "=r"(gen) : "l"(&g_gen) : "memory");
        __threadfence();
        unsigned prev = atomicAdd(&g_cnt, 1);
        if (prev == NCTA - 1) {
            g_cnt = 0;
            asm volatile("st.release.gpu.global.u32 [%0], %1;" :: "l"(&g_gen), "r"(gen + 1) : "memory");
        } else {
            unsigned cur;
            do {
                asm volatile("ld.acquire.gpu.global.u32 %0, [%1];" : "=r"(cur) : "l"(&g_gen) : "memory");
            } while (cur == gen);
        }
        __threadfence();
    }
    __syncthreads();
}

// =====================================================================
// Phase 1: x_gates (tf32 GEMM) -> [T][B][3S] fp32. Unchanged from r2.
// =====================================================================
#define XG_SMEM (2 * 2 * 128 * 36 * 4)

__global__ void __launch_bounds__(256) xg_kernel(const float* __restrict__ A,
                                                 const float* __restrict__ W,
                                                 const float* __restrict__ bias) {
    extern __shared__ float sm[];
    float* As = sm;
    float* Bs = sm + 2 * 128 * 36;

    const int tid = threadIdx.x;
    const size_t arow0 = (size_t)blockIdx.y * 128;
    const int    ncol0 = blockIdx.x * 128;

    auto load_stage = [&](int stage, int kc) {
        float* as = As + stage * 128 * 36;
        float* bs = Bs + stage * 128 * 36;
        #pragma unroll
        for (int i = 0; i < 4; i++) {
            int idx = tid + i * 256;
            int r = idx >> 3, c4 = (idx & 7) * 4;
            cp16(&as[r * 36 + c4], &A[(arow0 + r) * SDIM + kc + c4]);
            cp16(&bs[r * 36 + c4], &W[(size_t)(ncol0 + r) * SDIM + kc + c4]);
        }
    };

    const int wid = tid >> 5, lane = tid & 31, g = lane >> 2, tg = lane & 3;
    const int wm = wid & 3, wn = wid >> 2;

    float acc[2][8][4];
    #pragma unroll
    for (int i = 0; i < 2; i++)
        #pragma unroll
        for (int j = 0; j < 8; j++)
            #pragma unroll
            for (int k = 0; k < 4; k++) acc[i][j][k] = 0.f;

    load_stage(0, 0); cp_commit();
    for (int c = 0; c < SDIM / 32; ++c) {
        if (c + 1 < SDIM / 32) { load_stage((c + 1) & 1, (c + 1) * 32); cp_commit(); cp_wait<1>(); }
        else                   { cp_wait<0>(); }
        __syncthreads();
        const float* as = As + (c & 1) * 128 * 36;
        const float* bs = Bs + (c & 1) * 128 * 36;
        #pragma unroll
        for (int kk = 0; kk < 4; ++kk) {
            const int ko = kk * 8;
            unsigned a[2][4];
            #pragma unroll
            for (int mf = 0; mf < 2; ++mf) {
                int rb = wm * 32 + mf * 16;
                a[mf][0] = f2tf(as[(rb + g    ) * 36 + ko + tg    ]);
                a[mf][1] = f2tf(as[(rb + g + 8) * 36 + ko + tg    ]);
                a[mf][2] = f2tf(as[(rb + g    ) * 36 + ko + tg + 4]);
                a[mf][3] = f2tf(as[(rb + g + 8) * 36 + ko + tg + 4]);
            }
            #pragma unroll
            for (int nf = 0; nf < 8; ++nf) {
                int nb = wn * 64 + nf * 8 + g;
                unsigned b2[2];
                b2[0] = f2tf(bs[nb * 36 + ko + tg    ]);
                b2[1] = f2tf(bs[nb * 36 + ko + tg + 4]);
                mma8(acc[0][nf], a[0], b2);
                mma8(acc[1][nf], a[1], b2);
            }
        }
        __syncthreads();
    }
    #pragma unroll
    for (int mf = 0; mf < 2; ++mf) {
        #pragma unroll
        for (int nf = 0; nf < 8; ++nf) {
            int col = ncol0 + wn * 64 + nf * 8 + 2 * tg;
            float b0 = bias[col], b1 = bias[col + 1];
            size_t row = arow0 + wm * 32 + mf * 16 + g;       // = b*T + t
            size_t bb = row >> 10, tt = row & 1023;
            size_t orow0s = (tt << 6) + bb;
            size_t orow1s = orow0s + (8 << 6);
            float2 v0 = { acc[mf][nf][0] + b0, acc[mf][nf][1] + b1 };
            float2 v1 = { acc[mf][nf][2] + b0, acc[mf][nf][3] + b1 };
            *(float2*)&g_xg[orow0s * G3 + col] = v0;
            *(float2*)&g_xg[orow1s * G3 + col] = v1;
        }
    }
}

// =====================================================================
// Phase 2: persistent GRU scan, bf16 exchange + bf16 mma.
// 128 CTAs x 256 thr. CTA owns h cols [8c,8c+8) -> 24 gate rows (bf16,
// 24x1024 in SMEM, 49.5KB). h exchanged as bf16x2 [kp][b] (xor-swizzled),
// streamed in 8 chunks of 16KB via 4-stage bulk-copy pipeline.
// Warp w covers m=64 x its k16 slice per chunk; 8 k-partials reduced in
// SMEM. fp32 state kept in registers. x_gates prefetched via cp.async.
// =====================================================================
// smem words: 16 (mbar) + 4*4096 (stages) + 24*516 (ws) + 8*64*24 (hgs) + 1536 (xgs)
#define SCAN_SMEM ((16 + DEPTH*STG_W + NR*WS_STRIDE + 8*B64*NR + B64*NR) * 4)

__global__ void __launch_bounds__(256, 1) scan_kernel(const float* __restrict__ W_hh,
                                                      const float* __restrict__ b_hh) {
    extern __shared__ float sm[];
    uint64_t* mbar = (uint64_t*)sm;                     // 4 barriers
    float*    stg  = sm + 16;                           // 4 x 4096 words
    unsigned* ws   = (unsigned*)(stg + DEPTH * STG_W);  // 24 x 516 bf16x2 words
    float*    hgs  = (float*)(ws + NR * WS_STRIDE);     // 8 x 64 x 24 fp32 partials
    float*    xgs  = hgs + 8 * B64 * NR;                // 64 x 3 x 8 fp32

    const int tid  = threadIdx.x;
    const int col0 = blockIdx.x * WT;

    // ---- init: weights -> bf16x2 smem. rows [r(8); z(8); n(8)] of cols col0..col0+7
    for (int i = tid; i < NR * 512; i += 256) {
        int rr = i >> 9, kp = i & 511;
        int row = (rr >> 3) * SDIM + col0 + (rr & 7);
        const float2 v = *(const float2*)&W_hh[(size_t)row * SDIM + 2 * kp];
        ws[rr * WS_STRIDE + kp] = pack_bf(v.x, v.y);
    }
    // ---- zero own slice of h buffer 0
    {
        int b = tid >> 2, j2 = tid & 3;
        int kp = (col0 >> 1) + j2;
        g_h[0][kp * 64 + (b ^ (j2 << 3))] = 0u;
    }
    if (tid == 0)
        #pragma unroll
        for (int s = 0; s < DEPTH; ++s) mbar_init(&mbar[s], 1);

    // per-thread pointwise identity + persistent fp32 state + biases in regs
    const int pb = tid >> 2, pj2 = tid & 3;
    const int pc0 = col0 + 2 * pj2;
    float h0 = 0.f, h1 = 0.f;
    const float br0 = b_hh[pc0],            br1 = b_hh[pc0 + 1];
    const float bz0 = b_hh[SDIM + pc0],     bz1 = b_hh[SDIM + pc0 + 1];
    const float bn0 = b_hh[2 * SDIM + pc0], bn1 = b_hh[2 * SDIM + pc0 + 1];

    grid_barrier();

    const int w = tid >> 5, lane = tid & 31, g = lane >> 2, tg = lane & 3;
    const unsigned aoff  = (unsigned)((w * 8 + tg) * 64);   // stage word base for this thread's k16
    const unsigned asw   = (unsigned)(tg << 3);             // xor swizzle
    unsigned ph[DEPTH] = {0u, 0u, 0u, 0u};

    for (int t = 0; t < TLEN; ++t) {
        const unsigned* __restrict__ hcur = g_h[t & 1];
        unsigned*       __restrict__ hnxt = g_h[(t + 1) & 1];

        // prefetch this step's x_gates slice (consumed in epilogue)
        if (tid < 192) {
            int gate = tid >> 6, b = tid & 63;
            const float* src = &g_xg[(((size_t)t << 6) + b) * G3 + gate * SDIM + col0];
            float* dst = &xgs[b * 24 + gate * 8];
            cp16(dst, src);
            cp16(dst + 4, src + 4);
        }
        cp_commit();

        // prime pipeline: chunks 0..3
        if (tid == 0) {
            #pragma unroll
            for (int s = 0; s < DEPTH; ++s) {
                mbar_expect_tx(&mbar[s], STG_W * 4);
                bulkcp(stg + s * STG_W, hcur + s * STG_W, STG_W * 4, &mbar[s]);
            }
        }

        float acc[4][3][4];
        #pragma unroll
        for (int i = 0; i < 4; i++)
            #pragma unroll
            for (int j = 0; j < 3; j++)
                #pragma unroll
                for (int k = 0; k < 4; k++) acc[i][j][k] = 0.f;

        for (int c = 0; c < NCHUNK; ++c) {
            const int s = c & (DEPTH - 1);
            mbar_wait(&mbar[s], ph[s]);
            ph[s] ^= 1u;

            const unsigned* hb = (const unsigned*)(stg + s * STG_W) + aoff;
            unsigned a[4][4];
            #pragma unroll
            for (int mf = 0; mf < 4; ++mf) {
                unsigned m0 = (unsigned)(mf * 16 + g);
                a[mf][0] = hb[        (m0      ) ^ asw];
                a[mf][1] = hb[        (m0 + 8u ) ^ asw];
                a[mf][2] = hb[256u + ((m0      ) ^ asw)];
                a[mf][3] = hb[256u + ((m0 + 8u ) ^ asw)];
            }
            const int kw = c * 64 + w * 8 + tg;
            #pragma unroll
            for (int nf = 0; nf < 3; ++nf) {
                unsigned b2[2];
                const unsigned* wr = ws + (nf * 8 + g) * WS_STRIDE + kw;
                b2[0] = wr[0];
                b2[1] = wr[4];
                #pragma unroll
                for (int mf = 0; mf < 4; ++mf) mma16(acc[mf][nf], a[mf], b2);
            }
            __syncthreads();                 // stage s fully consumed
            if (tid == 0 && c + DEPTH < NCHUNK) {
                mbar_expect_tx(&mbar[s], STG_W * 4);
                bulkcp(stg + s * STG_W, hcur + (c + DEPTH) * STG_W, STG_W * 4, &mbar[s]);
            }
        }

        cp_wait<0>();                        // x_gates slice landed
        // stage k-partials
        #pragma unroll
        for (int mf = 0; mf < 4; ++mf) {
            #pragma unroll
            for (int nf = 0; nf < 3; ++nf) {
                int m = mf * 16 + g;
                int n = nf * 8 + 2 * tg;
                float* dst = &hgs[w * (B64 * NR) + m * NR + n];
                dst[0]          = acc[mf][nf][0];
                dst[1]          = acc[mf][nf][1];
                dst[8 * NR]     = acc[mf][nf][2];
                dst[8 * NR + 1] = acc[mf][nf][3];
            }
        }
        __syncthreads();

        // pointwise GRU update: thread owns (pb, cols pc0, pc0+1)
        {
            float hr0 = br0, hr1 = br1, hz0 = bz0, hz1 = bz1, hn0 = bn0, hn1 = bn1;
            #pragma unroll
            for (int q = 0; q < 8; ++q) {
                const float* base = &hgs[q * (B64 * NR) + pb * NR + 2 * pj2];
                hr0 += base[0];  hr1 += base[1];
                hz0 += base[8];  hz1 += base[9];
                hn0 += base[16]; hn1 += base[17];
            }
            const float* xr = &xgs[pb * 24 + 2 * pj2];
            float r0 = 1.f / (1.f + __expf(-(xr[0]  + hr0)));
            float r1 = 1.f / (1.f + __expf(-(xr[1]  + hr1)));
            float z0 = 1.f / (1.f + __expf(-(xr[8]  + hz0)));
            float z1 = 1.f / (1.f + __expf(-(xr[9]  + hz1)));
            float p0 = xr[16] + r0 * hn0;
            float p1 = xr[17] + r1 * hn1;
            float n0 = 2.f / (1.f + __expf(-2.f * p0)) - 1.f;
            float n1 = 2.f / (1.f + __expf(-2.f * p1)) - 1.f;
            h0 = (1.f - z0) * n0 + z0 * h0;
            h1 = (1.f - z1) * n1 + z1 * h1;
            int kp = (col0 >> 1) + pj2;
            hnxt[kp * 64 + (pb ^ (pj2 << 3))] = pack_bf(h0, h1);
            if (t == TLEN - 1) {
                g_hT[pb * SDIM + pc0]     = h0;
                g_hT[pb * SDIM + pc0 + 1] = h1;
            }
        }
        grid_barrier();
    }
}

// =====================================================================
// Phase 3: out[b] = sigmoid(g_hT[b] . W_out + b_out), fp32.
// =====================================================================
__global__ void final_kernel(const float* __restrict__ W_out,
                             const float* __restrict__ b_out,
                             float* __restrict__ out) {
    int wid = threadIdx.x >> 5, lane = threadIdx.x & 31;
    for (int b = wid; b < B64; b += 8) {
        const float* h = &g_hT[b * SDIM];
        float s = 0.f;
        for (int k = lane; k < SDIM; k += 32) s += h[k] * W_out[k];
        #pragma unroll
        for (int o = 16; o; o >>= 1) s += __shfl_xor_sync(0xffffffffu, s, o);
        if (lane == 0) out[b] = 1.f / (1.f + __expf(-(s + b_out[0])));
    }
}

// =====================================================================
extern "C" void kernel_launch(void* const* d_in, const int* in_sizes, int n_in,
                              void* d_out, int out_size) {
    const float* batch = (const float*)d_in[0];
    const float* W_ih  = (const float*)d_in[1];
    const float* W_hh  = (const float*)d_in[2];
    const float* b_ih  = (const float*)d_in[3];
    const float* b_hh  = (const float*)d_in[4];
    const float* W_out = (const float*)d_in[5];
    const float* b_out = (const float*)d_in[6];
    float* out = (float*)d_out;

    (void)in_sizes; (void)n_in; (void)out_size;

    cudaFuncSetAttribute(xg_kernel,   cudaFuncAttributeMaxDynamicSharedMemorySize, XG_SMEM);
    cudaFuncSetAttribute(scan_kernel, cudaFuncAttributeMaxDynamicSharedMemorySize, SCAN_SMEM);

    xg_kernel<<<dim3(G3 / 128, (B64 * TLEN) / 128), 256, XG_SMEM>>>(batch, W_ih, b_ih);
    scan_kernel<<<NCTA, 256, SCAN_SMEM>>>(W_hh, b_hh);
    final_kernel<<<1, 256>>>(W_out, b_out, out);
}

// round 13
// speedup vs baseline: 1.0092x; 1.0012x over previous
#include <cuda_runtime.h>
#include <cuda_bf16.h>
#include <cstdint>

#define B64  64
#define TLEN 1024
#define SDIM 1024
#define G3   (3*SDIM)

// ---- scan config ----
#define NCTA   128      // persistent CTAs; each owns WT h-columns
#define WT     8        // h columns per CTA
#define NR     24       // 3*WT gate rows (r,z,n)
#define NCHUNK 8        // k-chunks of 128 per step
#define DEPTH  4        // pipeline stages (16KB each)
#define STG_W  4096     // 32-bit words per stage (64 kp x 64 b)
#define WS_STRIDE 516   // padded word stride for weight rows

// ---- device globals (allocation-free scratch) ----
__device__ float    g_xg[(size_t)TLEN * B64 * G3];        // x_gates [T][B][3S] fp32
__device__ __align__(128) unsigned g_h[2][512 * B64];     // h bf16x2, [kp][b] xor-swizzled
__device__ float    g_hT[B64 * SDIM];                     // final h, fp32 [b][k]
__device__ unsigned g_cnt;
__device__ unsigned g_gen;

// ---------------- helpers ----------------
__device__ __forceinline__ unsigned f2tf(float f) {
    unsigned u;
    asm("cvt.rna.tf32.f32 %0, %1;" : "=r"(u) : "f"(f));
    return u;
}
__device__ __forceinline__ unsigned pack_bf(float lo, float hi) {
    unsigned r;
    asm("cvt.rn.bf16x2.f32 %0, %1, %2;" : "=r"(r) : "f"(hi), "f"(lo));
    return r;
}

// tf32 m16n8k8 (phase-1 GEMM)
__device__ __forceinline__ void mma8(float c[4], const unsigned a[4], const unsigned b[2]) {
    asm volatile(
        "mma.sync.aligned.m16n8k8.row.col.f32.tf32.tf32.f32 "
        "{%0,%1,%2,%3}, {%4,%5,%6,%7}, {%8,%9}, {%0,%1,%2,%3};"
        : "+f"(c[0]), "+f"(c[1]), "+f"(c[2]), "+f"(c[3])
        : "r"(a[0]), "r"(a[1]), "r"(a[2]), "r"(a[3]),
          "r"(b[0]), "r"(b[1]));
}
// bf16 m16n8k16 (scan GEMM)
__device__ __forceinline__ void mma16(float c[4], const unsigned a[4], const unsigned b[2]) {
    asm volatile(
        "mma.sync.aligned.m16n8k16.row.col.f32.bf16.bf16.f32 "
        "{%0,%1,%2,%3}, {%4,%5,%6,%7}, {%8,%9}, {%0,%1,%2,%3};"
        : "+f"(c[0]), "+f"(c[1]), "+f"(c[2]), "+f"(c[3])
        : "r"(a[0]), "r"(a[1]), "r"(a[2]), "r"(a[3]),
          "r"(b[0]), "r"(b[1]));
}

__device__ __forceinline__ void cp16(void* s, const void* g) {
    unsigned sa = (unsigned)__cvta_generic_to_shared(s);
    asm volatile("cp.async.cg.shared.global [%0], [%1], 16;" :: "r"(sa), "l"(g));
}
__device__ __forceinline__ void cp_commit() { asm volatile("cp.async.commit_group;"); }
template<int N> __device__ __forceinline__ void cp_wait() {
    asm volatile("cp.async.wait_group %0;" :: "n"(N));
}

__device__ __forceinline__ void bulkcp(void* dst_smem, const void* src, unsigned bytes, void* mbar) {
    unsigned d = (unsigned)__cvta_generic_to_shared(dst_smem);
    unsigned m = (unsigned)__cvta_generic_to_shared(mbar);
    asm volatile("cp.async.bulk.shared::cluster.global.mbarrier::complete_tx::bytes [%0], [%1], %2, [%3];"
                 :: "r"(d), "l"(src), "r"(bytes), "r"(m) : "memory");
}
__device__ __forceinline__ void mbar_init(void* mbar, unsigned cnt) {
    unsigned m = (unsigned)__cvta_generic_to_shared(mbar);
    asm volatile("mbarrier.init.shared.b64 [%0], %1;" :: "r"(m), "r"(cnt) : "memory");
}
__device__ __forceinline__ void mbar_expect_tx(void* mbar, unsigned bytes) {
    unsigned m = (unsigned)__cvta_generic_to_shared(mbar);
    asm volatile("mbarrier.arrive.expect_tx.shared.b64 _, [%0], %1;" :: "r"(m), "r"(bytes) : "memory");
}
__device__ __forceinline__ void mbar_wait(void* mbar, unsigned parity) {
    unsigned m = (unsigned)__cvta_generic_to_shared(mbar);
    asm volatile(
        "{\n\t"
        ".reg .pred P1;\n\t"
        "WAIT_LOOP_%=:\n\t"
        "mbarrier.try_wait.parity.acquire.cta.shared::cta.b64 P1, [%0], %1, 0x989680;\n\t"
        "@P1 bra.uni WAIT_DONE_%=;\n\t"
        "bra.uni WAIT_LOOP_%=;\n\t"
        "WAIT_DONE_%=:\n\t"
        "}"
        :: "r"(m), "r"(parity) : "memory");
}

__device__ __forceinline__ void grid_barrier() {
    __syncthreads();
    if (threadIdx.x == 0) {
        unsigned gen;
        asm volatile("ld.acquire.gpu.global.u32 %0, [%1];" : "=r"(gen) : "l"(&g_gen) : "memory");
        __threadfence();
        unsigned prev = atomicAdd(&g_cnt, 1);
        if (prev == NCTA - 1) {
            g_cnt = 0;
            asm volatile("st.release.gpu.global.u32 [%0], %1;" :: "l"(&g_gen), "r"(gen + 1) : "memory");
        } else {
            unsigned cur;
            do {
                asm volatile("ld.acquire.gpu.global.u32 %0, [%1];" : "=r"(cur) : "l"(&g_gen) : "memory");
            } while (cur == gen);
        }
        __threadfence();
    }
    __syncthreads();
}

// =====================================================================
// Phase 1: x_gates (tf32 GEMM) -> [T][B][3S] fp32. Unchanged from r2.
// =====================================================================
#define XG_SMEM (2 * 2 * 128 * 36 * 4)

__global__ void __launch_bounds__(256) xg_kernel(const float* __restrict__ A,
                                                 const float* __restrict__ W,
                                                 const float* __restrict__ bias) {
    extern __shared__ float sm[];
    float* As = sm;
    float* Bs = sm + 2 * 128 * 36;

    const int tid = threadIdx.x;
    const size_t arow0 = (size_t)blockIdx.y * 128;
    const int    ncol0 = blockIdx.x * 128;

    auto load_stage = [&](int stage, int kc) {
        float* as = As + stage * 128 * 36;
        float* bs = Bs + stage * 128 * 36;
        #pragma unroll
        for (int i = 0; i < 4; i++) {
            int idx = tid + i * 256;
            int r = idx >> 3, c4 = (idx & 7) * 4;
            cp16(&as[r * 36 + c4], &A[(arow0 + r) * SDIM + kc + c4]);
            cp16(&bs[r * 36 + c4], &W[(size_t)(ncol0 + r) * SDIM + kc + c4]);
        }
    };

    const int wid = tid >> 5, lane = tid & 31, g = lane >> 2, tg = lane & 3;
    const int wm = wid & 3, wn = wid >> 2;

    float acc[2][8][4];
    #pragma unroll
    for (int i = 0; i < 2; i++)
        #pragma unroll
        for (int j = 0; j < 8; j++)
            #pragma unroll
            for (int k = 0; k < 4; k++) acc[i][j][k] = 0.f;

    load_stage(0, 0); cp_commit();
    for (int c = 0; c < SDIM / 32; ++c) {
        if (c + 1 < SDIM / 32) { load_stage((c + 1) & 1, (c + 1) * 32); cp_commit(); cp_wait<1>(); }
        else                   { cp_wait<0>(); }
        __syncthreads();
        const float* as = As + (c & 1) * 128 * 36;
        const float* bs = Bs + (c & 1) * 128 * 36;
        #pragma unroll
        for (int kk = 0; kk < 4; ++kk) {
            const int ko = kk * 8;
            unsigned a[2][4];
            #pragma unroll
            for (int mf = 0; mf < 2; ++mf) {
                int rb = wm * 32 + mf * 16;
                a[mf][0] = f2tf(as[(rb + g    ) * 36 + ko + tg    ]);
                a[mf][1] = f2tf(as[(rb + g + 8) * 36 + ko + tg    ]);
                a[mf][2] = f2tf(as[(rb + g    ) * 36 + ko + tg + 4]);
                a[mf][3] = f2tf(as[(rb + g + 8) * 36 + ko + tg + 4]);
            }
            #pragma unroll
            for (int nf = 0; nf < 8; ++nf) {
                int nb = wn * 64 + nf * 8 + g;
                unsigned b2[2];
                b2[0] = f2tf(bs[nb * 36 + ko + tg    ]);
                b2[1] = f2tf(bs[nb * 36 + ko + tg + 4]);
                mma8(acc[0][nf], a[0], b2);
                mma8(acc[1][nf], a[1], b2);
            }
        }
        __syncthreads();
    }
    #pragma unroll
    for (int mf = 0; mf < 2; ++mf) {
        #pragma unroll
        for (int nf = 0; nf < 8; ++nf) {
            int col = ncol0 + wn * 64 + nf * 8 + 2 * tg;
            float b0 = bias[col], b1 = bias[col + 1];
            size_t row = arow0 + wm * 32 + mf * 16 + g;       // = b*T + t
            size_t bb = row >> 10, tt = row & 1023;
            size_t orow0s = (tt << 6) + bb;
            size_t orow1s = orow0s + (8 << 6);
            float2 v0 = { acc[mf][nf][0] + b0, acc[mf][nf][1] + b1 };
            float2 v1 = { acc[mf][nf][2] + b0, acc[mf][nf][3] + b1 };
            *(float2*)&g_xg[orow0s * G3 + col] = v0;
            *(float2*)&g_xg[orow1s * G3 + col] = v1;
        }
    }
}

// =====================================================================
// Phase 2: persistent GRU scan, bf16 exchange + bf16 mma.
// 128 CTAs x 256 thr. CTA owns h cols [8c,8c+8) -> 24 gate rows (bf16,
// 24x1024 in SMEM, 49.5KB). h exchanged as bf16x2 [kp][b] (xor-swizzled),
// streamed in 8 chunks of 16KB via 4-stage bulk-copy pipeline.
// Warp w covers m=64 x its k16 slice per chunk; 8 k-partials reduced in
// SMEM. fp32 state kept in registers. x_gates prefetched via cp.async.
// =====================================================================
// smem words: 16 (mbar) + 4*4096 (stages) + 24*516 (ws) + 8*64*24 (hgs) + 1536 (xgs)
#define SCAN_SMEM ((16 + DEPTH*STG_W + NR*WS_STRIDE + 8*B64*NR + B64*NR) * 4)

__global__ void __launch_bounds__(256, 1) scan_kernel(const float* __restrict__ W_hh,
                                                      const float* __restrict__ b_hh) {
    extern __shared__ float sm[];
    uint64_t* mbar = (uint64_t*)sm;                     // 4 barriers
    float*    stg  = sm + 16;                           // 4 x 4096 words
    unsigned* ws   = (unsigned*)(stg + DEPTH * STG_W);  // 24 x 516 bf16x2 words
    float*    hgs  = (float*)(ws + NR * WS_STRIDE);     // 8 x 64 x 24 fp32 partials
    float*    xgs  = hgs + 8 * B64 * NR;                // 64 x 3 x 8 fp32

    const int tid  = threadIdx.x;
    const int col0 = blockIdx.x * WT;

    // ---- init: weights -> bf16x2 smem. rows [r(8); z(8); n(8)] of cols col0..col0+7
    for (int i = tid; i < NR * 512; i += 256) {
        int rr = i >> 9, kp = i & 511;
        int row = (rr >> 3) * SDIM + col0 + (rr & 7);
        const float2 v = *(const float2*)&W_hh[(size_t)row * SDIM + 2 * kp];
        ws[rr * WS_STRIDE + kp] = pack_bf(v.x, v.y);
    }
    // ---- zero own slice of h buffer 0
    {
        int b = tid >> 2, j2 = tid & 3;
        int kp = (col0 >> 1) + j2;
        g_h[0][kp * 64 + (b ^ (j2 << 3))] = 0u;
    }
    if (tid == 0)
        #pragma unroll
        for (int s = 0; s < DEPTH; ++s) mbar_init(&mbar[s], 1);

    // per-thread pointwise identity + persistent fp32 state + biases in regs
    const int pb = tid >> 2, pj2 = tid & 3;
    const int pc0 = col0 + 2 * pj2;
    float h0 = 0.f, h1 = 0.f;
    const float br0 = b_hh[pc0],            br1 = b_hh[pc0 + 1];
    const float bz0 = b_hh[SDIM + pc0],     bz1 = b_hh[SDIM + pc0 + 1];
    const float bn0 = b_hh[2 * SDIM + pc0], bn1 = b_hh[2 * SDIM + pc0 + 1];

    grid_barrier();

    const int w = tid >> 5, lane = tid & 31, g = lane >> 2, tg = lane & 3;
    const unsigned aoff  = (unsigned)((w * 8 + tg) * 64);   // stage word base for this thread's k16
    const unsigned asw   = (unsigned)(tg << 3);             // xor swizzle
    unsigned ph[DEPTH] = {0u, 0u, 0u, 0u};

    for (int t = 0; t < TLEN; ++t) {
        const unsigned* __restrict__ hcur = g_h[t & 1];
        unsigned*       __restrict__ hnxt = g_h[(t + 1) & 1];

        // prefetch this step's x_gates slice (consumed in epilogue)
        if (tid < 192) {
            int gate = tid >> 6, b = tid & 63;
            const float* src = &g_xg[(((size_t)t << 6) + b) * G3 + gate * SDIM + col0];
            float* dst = &xgs[b * 24 + gate * 8];
            cp16(dst, src);
            cp16(dst + 4, src + 4);
        }
        cp_commit();

        // prime pipeline: chunks 0..3
        if (tid == 0) {
            #pragma unroll
            for (int s = 0; s < DEPTH; ++s) {
                mbar_expect_tx(&mbar[s], STG_W * 4);
                bulkcp(stg + s * STG_W, hcur + s * STG_W, STG_W * 4, &mbar[s]);
            }
        }

        float acc[4][3][4];
        #pragma unroll
        for (int i = 0; i < 4; i++)
            #pragma unroll
            for (int j = 0; j < 3; j++)
                #pragma unroll
                for (int k = 0; k < 4; k++) acc[i][j][k] = 0.f;

        for (int c = 0; c < NCHUNK; ++c) {
            const int s = c & (DEPTH - 1);
            mbar_wait(&mbar[s], ph[s]);
            ph[s] ^= 1u;

            const unsigned* hb = (const unsigned*)(stg + s * STG_W) + aoff;
            unsigned a[4][4];
            #pragma unroll
            for (int mf = 0; mf < 4; ++mf) {
                unsigned m0 = (unsigned)(mf * 16 + g);
                a[mf][0] = hb[        (m0      ) ^ asw];
                a[mf][1] = hb[        (m0 + 8u ) ^ asw];
                a[mf][2] = hb[256u + ((m0      ) ^ asw)];
                a[mf][3] = hb[256u + ((m0 + 8u ) ^ asw)];
            }
            const int kw = c * 64 + w * 8 + tg;
            #pragma unroll
            for (int nf = 0; nf < 3; ++nf) {
                unsigned b2[2];
                const unsigned* wr = ws + (nf * 8 + g) * WS_STRIDE + kw;
                b2[0] = wr[0];
                b2[1] = wr[4];
                #pragma unroll
                for (int mf = 0; mf < 4; ++mf) mma16(acc[mf][nf], a[mf], b2);
            }
            __syncthreads();                 // stage s fully consumed
            if (tid == 0 && c + DEPTH < NCHUNK) {
                mbar_expect_tx(&mbar[s], STG_W * 4);
                bulkcp(stg + s * STG_W, hcur + (c + DEPTH) * STG_W, STG_W * 4, &mbar[s]);
            }
        }

        cp_wait<0>();                        // x_gates slice landed
        // stage k-partials
        #pragma unroll
        for (int mf = 0; mf < 4; ++mf) {
            #pragma unroll
            for (int nf = 0; nf < 3; ++nf) {
                int m = mf * 16 + g;
                int n = nf * 8 + 2 * tg;
                float* dst = &hgs[w * (B64 * NR) + m * NR + n];
                dst[0]          = acc[mf][nf][0];
                dst[1]          = acc[mf][nf][1];
                dst[8 * NR]     = acc[mf][nf][2];
                dst[8 * NR + 1] = acc[mf][nf][3];
            }
        }
        __syncthreads();

        // pointwise GRU update: thread owns (pb, cols pc0, pc0+1)
        {
            float hr0 = br0, hr1 = br1, hz0 = bz0, hz1 = bz1, hn0 = bn0, hn1 = bn1;
            #pragma unroll
            for (int q = 0; q < 8; ++q) {
                const float* base = &hgs[q * (B64 * NR) + pb * NR + 2 * pj2];
                hr0 += base[0];  hr1 += base[1];
                hz0 += base[8];  hz1 += base[9];
                hn0 += base[16]; hn1 += base[17];
            }
            const float* xr = &xgs[pb * 24 + 2 * pj2];
            float r0 = 1.f / (1.f + __expf(-(xr[0]  + hr0)));
            float r1 = 1.f / (1.f + __expf(-(xr[1]  + hr1)));
            float z0 = 1.f / (1.f + __expf(-(xr[8]  + hz0)));
            float z1 = 1.f / (1.f + __expf(-(xr[9]  + hz1)));
            float p0 = xr[16] + r0 * hn0;
            float p1 = xr[17] + r1 * hn1;
            float n0 = 2.f / (1.f + __expf(-2.f * p0)) - 1.f;
            float n1 = 2.f / (1.f + __expf(-2.f * p1)) - 1.f;
            h0 = (1.f - z0) * n0 + z0 * h0;
            h1 = (1.f - z1) * n1 + z1 * h1;
            int kp = (col0 >> 1) + pj2;
            hnxt[kp * 64 + (pb ^ (pj2 << 3))] = pack_bf(h0, h1);
            if (t == TLEN - 1) {
                g_hT[pb * SDIM + pc0]     = h0;
                g_hT[pb * SDIM + pc0 + 1] = h1;
            }
        }
        grid_barrier();
    }
}

// =====================================================================
// Phase 3: out[b] = sigmoid(g_hT[b] . W_out + b_out), fp32.
// =====================================================================
__global__ void final_kernel(const float* __restrict__ W_out,
                             const float* __restrict__ b_out,
                             float* __restrict__ out) {
    int wid = threadIdx.x >> 5, lane = threadIdx.x & 31;
    for (int b = wid; b < B64; b += 8) {
        const float* h = &g_hT[b * SDIM];
        float s = 0.f;
        for (int k = lane; k < SDIM; k += 32) s += h[k] * W_out[k];
        #pragma unroll
        for (int o = 16; o; o >>= 1) s += __shfl_xor_sync(0xffffffffu, s, o);
        if (lane == 0) out[b] = 1.f / (1.f + __expf(-(s + b_out[0])));
    }
}

// =====================================================================
extern "C" void kernel_launch(void* const* d_in, const int* in_sizes, int n_in,
                              void* d_out, int out_size) {
    const float* batch = (const float*)d_in[0];
    const float* W_ih  = (const float*)d_in[1];
    const float* W_hh  = (const float*)d_in[2];
    const float* b_ih  = (const float*)d_in[3];
    const float* b_hh  = (const float*)d_in[4];
    const float* W_out = (const float*)d_in[5];
    const float* b_out = (const float*)d_in[6];
    float* out = (float*)d_out;

    (void)in_sizes; (void)n_in; (void)out_size;

    cudaFuncSetAttribute(xg_kernel,   cudaFuncAttributeMaxDynamicSharedMemorySize, XG_SMEM);
    cudaFuncSetAttribute(scan_kernel, cudaFuncAttributeMaxDynamicSharedMemorySize, SCAN_SMEM);

    xg_kernel<<<dim3(G3 / 128, (B64 * TLEN) / 128), 256, XG_SMEM>>>(batch, W_ih, b_ih);
    scan_kernel<<<NCTA, 256, SCAN_SMEM>>>(W_hh, b_hh);
    final_kernel<<<1, 256>>>(W_out, b_out, out);
}